// round 12
// baseline (speedup 1.0000x reference)
#include <cuda_runtime.h>
#include <cuda_fp16.h>
#include <math.h>
#include <stdint.h>

// ---------------------------------------------------------------------------
// NSF coupling layer on GB300 (compute_103-safe tensor path).
//   GEMMs: mma.sync.m16n8k16.f32.f16.f16.f32, single-term fp16.
//   CTA 128x128, BK=64, 4 warps (warp tile 64x64 => 16 MAC/smem-byte),
//   3 CTAs/SM (12 warps) — smem-port-bound model from R11 ncu.
//   2-stage cp.async double buffer. Fused weight transposes.
// ---------------------------------------------------------------------------

#define MAXB 32768
#define HD   512
#define PDIM 1472
#define PPAD 1536

// ------------------------- scratch (device globals) ------------------------
__device__ __align__(128) __half g_xl[(size_t)MAXB * 64];
__device__ __align__(128) __half g_up[(size_t)MAXB * 64];
__device__ __align__(128) __half g_hA[(size_t)MAXB * HD];
__device__ __align__(128) __half g_hB[(size_t)MAXB * HD];
__device__ __align__(128) float g_params[(size_t)MAXB * PDIM];
__device__ __align__(128) float g_ld[MAXB];
__device__ __align__(128) __half g_w1t[512 * 64];
__device__ __align__(128) __half g_w2t[512 * 512];
__device__ __align__(128) __half g_w3t[PPAD * 512];
__device__ __align__(128) __half g_v1t[512 * 64];
__device__ __align__(128) __half g_v2t[512 * 512];
__device__ __align__(128) __half g_v3t[PPAD * 512];

// ------------------------- low-level helpers -------------------------------
__device__ __forceinline__ uint32_t smem_u32(const void* p) {
    uint32_t a;
    asm("{ .reg .u64 t; cvta.to.shared.u64 t, %1; cvt.u32.u64 %0, t; }"
        : "=r"(a) : "l"(p));
    return a;
}

__device__ __forceinline__ void ldsm4(uint32_t* r, uint32_t addr) {
    asm volatile("ldmatrix.sync.aligned.m8n8.x4.shared.b16 {%0,%1,%2,%3}, [%4];"
                 : "=r"(r[0]), "=r"(r[1]), "=r"(r[2]), "=r"(r[3]) : "r"(addr));
}

__device__ __forceinline__ void mma16816(float* c, const uint32_t* a,
                                         const uint32_t* b) {
    asm volatile(
        "mma.sync.aligned.m16n8k16.row.col.f32.f16.f16.f32 "
        "{%0,%1,%2,%3}, {%4,%5,%6,%7}, {%8,%9}, {%0,%1,%2,%3};"
        : "+f"(c[0]), "+f"(c[1]), "+f"(c[2]), "+f"(c[3])
        : "r"(a[0]), "r"(a[1]), "r"(a[2]), "r"(a[3]), "r"(b[0]), "r"(b[1]));
}

#define CP_ASYNC16(sa, gp) \
    asm volatile("cp.async.cg.shared.global [%0], [%1], 16;" :: "r"(sa), "l"(gp))
#define CP_COMMIT() asm volatile("cp.async.commit_group;" ::: "memory")
#define CP_WAIT0()  asm volatile("cp.async.wait_group 0;" ::: "memory")

// ---------------------------------------------------------------------------
// HMMA GEMM:  C[M, Nreal] = A[M,K] @ Wt[Npad,K]^T + bias  (opt SiLU)
// CTA 128x128, BK=64, 4 warps (2 M x 2 N), warp tile 64x64, fp16 operands.
// SMEM tile per matrix: 128 rows x 64 fp16 (128 B/row), SW128 swizzle:
//   phys = row*128 + ((chunk16 ^ (row & 7)) << 4)
// Stage = {A, B} = 2 * 16KB = 32KB; two stages = 64KB; 3 CTAs/SM (192KB).
// ---------------------------------------------------------------------------
#define STAGE_BYTES 32768

__device__ __forceinline__ void load_stage(
    uint32_t sbase,
    const __half* a, const __half* b,
    int lda, int ldb, int tid)
{
#pragma unroll
    for (int it = 0; it < 16; it++) {
        const int idx = it * 128 + tid;
        const int mat = idx >> 10;        // 0 = A, 1 = B
        const int cid = idx & 1023;
        const int row = cid >> 3;
        const int ch  = cid & 7;
        const int ld  = (mat == 0) ? lda : ldb;
        const __half* g = (mat == 0) ? a : b;
        const void* gp = g + (size_t)row * ld + ch * 8;
        const uint32_t sa =
            sbase + mat * 16384 + row * 128 + ((ch ^ (row & 7)) << 4);
        CP_ASYNC16(sa, gp);
    }
}

template <int ACT, int SPLIT>
__global__ __launch_bounds__(128, 3)
void gemm_hmma(const __half* __restrict__ A, int lda,
               const __half* __restrict__ B,
               const float* __restrict__ bias,
               float* __restrict__ outf,
               __half* __restrict__ oh,
               int Nreal, int K)
{
    extern __shared__ char smem[];
    const uint32_t sbase = smem_u32(smem);

    const int tid  = threadIdx.x;
    const int lane = tid & 31;
    const int wid  = tid >> 5;            // 0..3
    const int warp_m = (wid >> 1) * 64;   // 0 or 64
    const int warp_n = (wid & 1) * 64;    // 0 or 64
    const int m0 = blockIdx.y * 128;
    const int n0 = blockIdx.x * 128;

    const __half* Ap = A + (size_t)m0 * lda;
    const __half* Bp = B + (size_t)n0 * K;

    float acc[4][8][4];
#pragma unroll
    for (int i = 0; i < 4; i++)
#pragma unroll
        for (int j = 0; j < 8; j++)
#pragma unroll
            for (int q = 0; q < 4; q++) acc[i][j][q] = 0.f;

    const int nk = K >> 6;  // BK = 64

    // prologue: prefetch stage 0
    load_stage(sbase, Ap, Bp, lda, K, tid);
    CP_COMMIT();

    for (int kc = 0; kc < nk; kc++) {
        CP_WAIT0();           // stage kc arrived
        __syncthreads();      // all warps done reading the other buffer

        if (kc + 1 < nk) {    // prefetch next chunk into other buffer
            const int ko = (kc + 1) * 64;
            load_stage(sbase + ((kc + 1) & 1) * STAGE_BYTES,
                       Ap + ko, Bp + ko, lda, K, tid);
            CP_COMMIT();
        }

        const uint32_t st = sbase + (kc & 1) * STAGE_BYTES;
        const uint32_t aB = st, bB = st + 16384;

#pragma unroll
        for (int s = 0; s < 4; s++) {  // four k16 steps per chunk
            uint32_t ah[4][4];
            const int chA = s * 2 + (lane >> 4);
#pragma unroll
            for (int i = 0; i < 4; i++) {
                const int r = warp_m + i * 16 + (lane & 15);
                const uint32_t off = r * 128 + ((chA ^ (r & 7)) << 4);
                ldsm4(ah[i], aB + off);
            }
            // B fragments loaded just-in-time per 16-col group: keeps live
            // registers low (fits 3 CTAs/SM) and interleaves LDSM with HMMA.
            const int chB = s * 2 + ((lane >> 3) & 1);
#pragma unroll
            for (int j2 = 0; j2 < 4; j2++) {
                uint32_t bh[4];
                const int n = warp_n + j2 * 16 + (lane & 7) + ((lane >> 4) << 3);
                const uint32_t off = n * 128 + ((chB ^ (n & 7)) << 4);
                ldsm4(bh, bB + off);
#pragma unroll
                for (int i = 0; i < 4; i++) {
                    mma16816(acc[i][j2 * 2 + 0], ah[i], &bh[0]);
                    mma16816(acc[i][j2 * 2 + 1], ah[i], &bh[2]);
                }
            }
        }
        // next iteration's __syncthreads() guards the buffer swap
    }

    // ---- epilogue: bias + opt SiLU + store (fp32 or fp16) ----
#pragma unroll
    for (int i = 0; i < 4; i++) {
        const int r0 = m0 + warp_m + i * 16 + (lane >> 2);
#pragma unroll
        for (int j = 0; j < 8; j++) {
            const int col = n0 + warp_n + j * 8 + ((lane & 3) << 1);
            if (col < Nreal) {
                const float b0 = bias[col];
                const float b1 = bias[col + 1];
#pragma unroll
                for (int h = 0; h < 2; h++) {
                    const int r = r0 + h * 8;
                    float v0 = acc[i][j][h * 2 + 0] + b0;
                    float v1 = acc[i][j][h * 2 + 1] + b1;
                    if (ACT) {
                        v0 = v0 / (1.f + __expf(-v0));
                        v1 = v1 / (1.f + __expf(-v1));
                    }
                    const size_t ob = (size_t)r * Nreal + col;
                    if (SPLIT) {
                        *reinterpret_cast<__half2*>(oh + ob) =
                            __halves2half2(__float2half(v0), __float2half(v1));
                    } else {
                        float2 v; v.x = v0; v.y = v1;
                        *reinterpret_cast<float2*>(outf + ob) = v;
                    }
                }
            }
        }
    }
}

// ---------------------------------------------------------------------------
// prep: x lower half -> fp16
// ---------------------------------------------------------------------------
__global__ void prep_x_kernel(const float* __restrict__ x,
                              __half* __restrict__ hx, int total)
{
    int idx = blockIdx.x * blockDim.x + threadIdx.x;
    if (idx >= total) return;
    int b = idx >> 6, j = idx & 63;
    hx[idx] = __float2half(x[(size_t)b * 128 + j]);
}

// ---------------------------------------------------------------------------
// Fused weight transpose: all 6 weights (both networks) in one launch.
// Per-job tiles: w1 32, w2 256, w3 768 (x2 nets); offsets below.
// ---------------------------------------------------------------------------
__global__ __launch_bounds__(256)
void conv_all_kernel(const float* W1a, __half* T1a,
                     const float* W2a, __half* T2a,
                     const float* W3a, __half* T3a,
                     const float* W1b, __half* T1b,
                     const float* W2b, __half* T2b,
                     const float* W3b, __half* T3b)
{
    __shared__ float t[32][33];
    const int bid = blockIdx.x;

    const float* W; __half* Wt; int K, N, Npad, loc;
    if (bid < 32)        { W = W1a; Wt = T1a; K = 64;  N = 512;  Npad = 512;  loc = bid; }
    else if (bid < 288)  { W = W2a; Wt = T2a; K = 512; N = 512;  Npad = 512;  loc = bid - 32; }
    else if (bid < 1056) { W = W3a; Wt = T3a; K = 512; N = PDIM; Npad = PPAD; loc = bid - 288; }
    else if (bid < 1088) { W = W1b; Wt = T1b; K = 64;  N = 512;  Npad = 512;  loc = bid - 1056; }
    else if (bid < 1344) { W = W2b; Wt = T2b; K = 512; N = 512;  Npad = 512;  loc = bid - 1088; }
    else                 { W = W3b; Wt = T3b; K = 512; N = PDIM; Npad = PPAD; loc = bid - 1344; }

    const int tiles_x = Npad >> 5;
    const int n0 = (loc % tiles_x) * 32;
    const int k0 = (loc / tiles_x) * 32;
    const int tx = threadIdx.x & 31;
    const int ty = threadIdx.x >> 5;   // 0..7

    const int n = n0 + tx;
#pragma unroll
    for (int i = 0; i < 32; i += 8) {
        const int k = k0 + ty + i;
        t[ty + i][tx] = (n < N) ? W[(size_t)k * N + n] : 0.f;
    }
    __syncthreads();

#pragma unroll
    for (int i = 0; i < 32; i += 8) {
        const int nn = n0 + ty + i;
        const int kk = k0 + tx;
        Wt[(size_t)nn * K + kk] = __float2half(t[tx][ty + i]);
    }
}

// ---------------------------------------------------------------------------
// RQS spline + logdet. Coalesced SMEM-staged parameter loads.
// ---------------------------------------------------------------------------
__device__ __forceinline__ float softplusf(float v)
{
    return (v > 20.f) ? v : log1pf(expf(v));
}

__global__ __launch_bounds__(64)
void rqs_kernel(const float* __restrict__ x,
                const float* __restrict__ params,
                __half* __restrict__ up,
                float* __restrict__ dout,
                float* __restrict__ ld_buf,
                int phase, int Bn)
{
    const int b = blockIdx.x;
    const int j = threadIdx.x;  // 0..63

    __shared__ __align__(16) float sp[PDIM];
    {
        const float4* src = reinterpret_cast<const float4*>(
            params + (size_t)b * PDIM);
        float4* dst = reinterpret_cast<float4*>(sp);
#pragma unroll
        for (int i = 0; i < 6; i++) {
            const int q = i * 64 + j;
            if (q < PDIM / 4) dst[q] = src[q];
        }
    }
    const float xv = x[(size_t)b * 128 + (phase == 0 ? 64 + j : j)];
    __syncthreads();

    const float* p = sp + j * 23;  // stride 23: conflict-free

    float W[8], H[8], D7[7];
#pragma unroll
    for (int i = 0; i < 8; i++) W[i] = p[i];
#pragma unroll
    for (int i = 0; i < 8; i++) H[i] = p[8 + i];
#pragma unroll
    for (int i = 0; i < 7; i++) D7[i] = p[16 + i];

    float mw = W[0];
#pragma unroll
    for (int i = 1; i < 8; i++) mw = fmaxf(mw, W[i]);
    float sw = 0.f;
#pragma unroll
    for (int i = 0; i < 8; i++) { W[i] = expf(W[i] - mw); sw += W[i]; }
    const float invw = 1.f / sw;

    float mh = H[0];
#pragma unroll
    for (int i = 1; i < 8; i++) mh = fmaxf(mh, H[i]);
    float sh = 0.f;
#pragma unroll
    for (int i = 0; i < 8; i++) { H[i] = expf(H[i] - mh); sh += H[i]; }
    const float invh = 1.f / sh;

    float cumw[9], cumh[9];
    cumw[0] = 0.f; cumh[0] = 0.f;
#pragma unroll
    for (int i = 0; i < 8; i++) {
        cumw[i + 1] = cumw[i] + (0.001f + 0.992f * W[i] * invw);
        cumh[i + 1] = cumh[i] + (0.001f + 0.992f * H[i] * invh);
    }
#pragma unroll
    for (int i = 0; i < 9; i++) {
        cumw[i] = 2.f * cumw[i] - 1.f;
        cumh[i] = 2.f * cumh[i] - 1.f;
    }
    cumw[0] = -1.f; cumw[8] = 1.f;
    cumh[0] = -1.f; cumh[8] = 1.f;

    float d[9];
    const float CST = logf(expf(1.0f - 0.001f) - 1.0f);
    const float dpad = 0.001f + softplusf(CST);
    d[0] = dpad; d[8] = dpad;
#pragma unroll
    for (int i = 0; i < 7; i++) d[i + 1] = 0.001f + softplusf(D7[i]);

    int idx = 0;
#pragma unroll
    for (int i = 0; i < 9; i++) {
        float loc = cumw[i] + ((i == 8) ? 1e-6f : 0.f);
        idx += (xv >= loc) ? 1 : 0;
    }
    idx -= 1;
    idx = max(0, min(7, idx));

    float icw = 0.f, iw = 1.f, ich = 0.f, ih = 1.f, d0 = 1.f, d1 = 1.f;
#pragma unroll
    for (int i = 0; i < 8; i++) {
        if (i == idx) {
            icw = cumw[i]; iw = cumw[i + 1] - cumw[i];
            ich = cumh[i]; ih = cumh[i + 1] - cumh[i];
            d0 = d[i]; d1 = d[i + 1];
        }
    }
    const float idel = ih / iw;
    const float th   = (xv - icw) / iw;
    const float omt  = 1.f - th;
    const float t1mt = th * omt;

    const float numer = ih * (idel * th * th + d0 * t1mt);
    const float den   = idel + (d0 + d1 - 2.f * idel) * t1mt;
    float out = ich + numer / den;

    const float dnum = idel * idel *
        (d1 * th * th + 2.f * idel * t1mt + d0 * omt * omt);
    float lad = logf(dnum) - 2.f * logf(den);

    const bool inside = (xv >= -1.f) && (xv <= 1.f);
    if (!inside) { out = xv; lad = 0.f; }

    if (phase == 0) {
        dout[(size_t)b * 128 + 64 + j] = out;
        up[(size_t)b * 64 + j] = __float2half(out);
    } else {
        dout[(size_t)b * 128 + j] = out;
    }

    float v = lad;
#pragma unroll
    for (int off = 16; off > 0; off >>= 1)
        v += __shfl_down_sync(0xffffffffu, v, off);
    __shared__ float sred[2];
    if ((j & 31) == 0) sred[j >> 5] = v;
    __syncthreads();
    if (j == 0) {
        const float tot = sred[0] + sred[1];
        if (phase == 0) ld_buf[b] = tot;
        else dout[(size_t)Bn * 128 + b] = ld_buf[b] + tot;
    }
}

// ---------------------------------------------------------------------------
// Launch
// ---------------------------------------------------------------------------
extern "C" void kernel_launch(void* const* d_in, const int* in_sizes, int n_in,
                              void* d_out, int out_size)
{
    const float* x    = (const float*)d_in[0];
    const float* f1w1 = (const float*)d_in[1];
    const float* f1b1 = (const float*)d_in[2];
    const float* f1w2 = (const float*)d_in[3];
    const float* f1b2 = (const float*)d_in[4];
    const float* f1w3 = (const float*)d_in[5];
    const float* f1b3 = (const float*)d_in[6];
    const float* f2w1 = (const float*)d_in[7];
    const float* f2b1 = (const float*)d_in[8];
    const float* f2w2 = (const float*)d_in[9];
    const float* f2b2 = (const float*)d_in[10];
    const float* f2w3 = (const float*)d_in[11];
    const float* f2b3 = (const float*)d_in[12];
    float* out = (float*)d_out;

    const int B = in_sizes[0] / 128;

    __half *xl, *up, *hA, *hB, *w1, *w2, *w3, *v1, *v2, *v3;
    float *pa, *ld;
    cudaGetSymbolAddress((void**)&xl, g_xl);
    cudaGetSymbolAddress((void**)&up, g_up);
    cudaGetSymbolAddress((void**)&hA, g_hA);
    cudaGetSymbolAddress((void**)&hB, g_hB);
    cudaGetSymbolAddress((void**)&w1, g_w1t);
    cudaGetSymbolAddress((void**)&w2, g_w2t);
    cudaGetSymbolAddress((void**)&w3, g_w3t);
    cudaGetSymbolAddress((void**)&v1, g_v1t);
    cudaGetSymbolAddress((void**)&v2, g_v2t);
    cudaGetSymbolAddress((void**)&v3, g_v3t);
    cudaGetSymbolAddress((void**)&pa, g_params);
    cudaGetSymbolAddress((void**)&ld, g_ld);

    const int DSMEM = 2 * STAGE_BYTES;  // 64 KB
    cudaFuncSetAttribute((const void*)gemm_hmma<1, 1>,
                         cudaFuncAttributeMaxDynamicSharedMemorySize, DSMEM);
    cudaFuncSetAttribute((const void*)gemm_hmma<0, 0>,
                         cudaFuncAttributeMaxDynamicSharedMemorySize, DSMEM);

    const int MB = B / 128;

    // prep + ALL weight conversions up front (independent of everything)
    prep_x_kernel<<<(B * 64 + 255) / 256, 256>>>(x, xl, B * 64);
    conv_all_kernel<<<2112, 256>>>(f1w1, w1, f1w2, w2, f1w3, w3,
                                   f2w1, v1, f2w2, v2, f2w3, v3);

    // ---- FCNN1 ----
    gemm_hmma<1, 1><<<dim3(4, MB), 128, DSMEM>>>(xl, 64, w1, f1b1,
                                                 nullptr, hA, 512, 64);
    gemm_hmma<1, 1><<<dim3(4, MB), 128, DSMEM>>>(hA, 512, w2, f1b2,
                                                 nullptr, hB, 512, 512);
    gemm_hmma<0, 0><<<dim3(PPAD / 128, MB), 128, DSMEM>>>(hB, 512, w3, f1b3,
                                                          pa, nullptr, PDIM, 512);

    rqs_kernel<<<B, 64>>>(x, pa, up, out, ld, 0, B);

    // ---- FCNN2 ----
    gemm_hmma<1, 1><<<dim3(4, MB), 128, DSMEM>>>(up, 64, v1, f2b1,
                                                 nullptr, hA, 512, 64);
    gemm_hmma<1, 1><<<dim3(4, MB), 128, DSMEM>>>(hA, 512, v2, f2b2,
                                                 nullptr, hB, 512, 512);
    gemm_hmma<0, 0><<<dim3(PPAD / 128, MB), 128, DSMEM>>>(hB, 512, v3, f2b3,
                                                          pa, nullptr, PDIM, 512);

    rqs_kernel<<<B, 64>>>(x, pa, nullptr, out, ld, 1, B);
}

// round 13
// speedup vs baseline: 1.2151x; 1.2151x over previous
#include <cuda_runtime.h>
#include <cuda_fp16.h>
#include <math.h>
#include <stdint.h>

// ---------------------------------------------------------------------------
// NSF coupling layer on GB300 (compute_103-safe tensor path).
//   GEMMs: mma.sync.m16n8k16.f32.f16.f16.f32, single-term fp16.
//   CTA 128x128, BK=64, 8 warps (warp tile 64x32), 2-stage cp.async,
//   2 CTAs/SM (R9/R11 optimum). Spline params stored fp16 (halves the
//   param DRAM stream feeding the RQS kernels).
// ---------------------------------------------------------------------------

#define MAXB 32768
#define HD   512
#define PDIM 1472
#define PPAD 1536

// ------------------------- scratch (device globals) ------------------------
__device__ __align__(128) __half g_xl[(size_t)MAXB * 64];
__device__ __align__(128) __half g_up[(size_t)MAXB * 64];
__device__ __align__(128) __half g_hA[(size_t)MAXB * HD];
__device__ __align__(128) __half g_hB[(size_t)MAXB * HD];
__device__ __align__(128) __half g_params[(size_t)MAXB * PDIM];
__device__ __align__(128) float g_ld[MAXB];
__device__ __align__(128) __half g_w1t[512 * 64];
__device__ __align__(128) __half g_w2t[512 * 512];
__device__ __align__(128) __half g_w3t[PPAD * 512];
__device__ __align__(128) __half g_v1t[512 * 64];
__device__ __align__(128) __half g_v2t[512 * 512];
__device__ __align__(128) __half g_v3t[PPAD * 512];

// ------------------------- low-level helpers -------------------------------
__device__ __forceinline__ uint32_t smem_u32(const void* p) {
    uint32_t a;
    asm("{ .reg .u64 t; cvta.to.shared.u64 t, %1; cvt.u32.u64 %0, t; }"
        : "=r"(a) : "l"(p));
    return a;
}

__device__ __forceinline__ void ldsm4(uint32_t* r, uint32_t addr) {
    asm volatile("ldmatrix.sync.aligned.m8n8.x4.shared.b16 {%0,%1,%2,%3}, [%4];"
                 : "=r"(r[0]), "=r"(r[1]), "=r"(r[2]), "=r"(r[3]) : "r"(addr));
}

__device__ __forceinline__ void mma16816(float* c, const uint32_t* a,
                                         const uint32_t* b) {
    asm volatile(
        "mma.sync.aligned.m16n8k16.row.col.f32.f16.f16.f32 "
        "{%0,%1,%2,%3}, {%4,%5,%6,%7}, {%8,%9}, {%0,%1,%2,%3};"
        : "+f"(c[0]), "+f"(c[1]), "+f"(c[2]), "+f"(c[3])
        : "r"(a[0]), "r"(a[1]), "r"(a[2]), "r"(a[3]), "r"(b[0]), "r"(b[1]));
}

#define CP_ASYNC16(sa, gp) \
    asm volatile("cp.async.cg.shared.global [%0], [%1], 16;" :: "r"(sa), "l"(gp))
#define CP_COMMIT() asm volatile("cp.async.commit_group;" ::: "memory")
#define CP_WAIT0()  asm volatile("cp.async.wait_group 0;" ::: "memory")

// ---------------------------------------------------------------------------
// HMMA GEMM:  C[M, Nreal] = A[M,K] @ Wt[Npad,K]^T + bias  (opt SiLU)
// CTA 128x128, BK=64, 8 warps (2 M x 4 N), warp tile 64x32, fp16 operands.
// SMEM tile per matrix: 128 rows x 64 fp16 (128 B/row), SW128 swizzle:
//   phys = row*128 + ((chunk16 ^ (row & 7)) << 4)
// Stage = {A, B} = 2 * 16KB = 32KB; two stages = 64KB; 2 CTAs/SM.
// ---------------------------------------------------------------------------
#define STAGE_BYTES 32768

__device__ __forceinline__ void load_stage(
    uint32_t sbase,
    const __half* a, const __half* b,
    int lda, int ldb, int tid)
{
#pragma unroll
    for (int it = 0; it < 8; it++) {
        const int idx = it * 256 + tid;
        const int mat = idx >> 10;        // 0 = A, 1 = B
        const int cid = idx & 1023;
        const int row = cid >> 3;
        const int ch  = cid & 7;
        const int ld  = (mat == 0) ? lda : ldb;
        const __half* g = (mat == 0) ? a : b;
        const void* gp = g + (size_t)row * ld + ch * 8;
        const uint32_t sa =
            sbase + mat * 16384 + row * 128 + ((ch ^ (row & 7)) << 4);
        CP_ASYNC16(sa, gp);
    }
}

template <int ACT>
__global__ __launch_bounds__(256, 2)
void gemm_hmma(const __half* __restrict__ A, int lda,
               const __half* __restrict__ B,
               const float* __restrict__ bias,
               __half* __restrict__ oh,
               int Nreal, int K)
{
    extern __shared__ char smem[];
    const uint32_t sbase = smem_u32(smem);

    const int tid  = threadIdx.x;
    const int lane = tid & 31;
    const int wid  = tid >> 5;
    const int warp_m = (wid >> 2) * 64;   // 0 or 64
    const int warp_n = (wid & 3) * 32;    // 0,32,64,96
    const int m0 = blockIdx.y * 128;
    const int n0 = blockIdx.x * 128;

    const __half* Ap = A + (size_t)m0 * lda;
    const __half* Bp = B + (size_t)n0 * K;

    float acc[4][4][4];
#pragma unroll
    for (int i = 0; i < 4; i++)
#pragma unroll
        for (int j = 0; j < 4; j++)
#pragma unroll
            for (int q = 0; q < 4; q++) acc[i][j][q] = 0.f;

    const int nk = K >> 6;  // BK = 64

    // prologue: prefetch stage 0
    load_stage(sbase, Ap, Bp, lda, K, tid);
    CP_COMMIT();

    for (int kc = 0; kc < nk; kc++) {
        CP_WAIT0();           // stage kc arrived
        __syncthreads();      // all warps done reading the other buffer

        if (kc + 1 < nk) {    // prefetch next chunk into other buffer
            const int ko = (kc + 1) * 64;
            load_stage(sbase + ((kc + 1) & 1) * STAGE_BYTES,
                       Ap + ko, Bp + ko, lda, K, tid);
            CP_COMMIT();
        }

        const uint32_t st = sbase + (kc & 1) * STAGE_BYTES;
        const uint32_t aB = st, bB = st + 16384;

#pragma unroll
        for (int s = 0; s < 4; s++) {  // four k16 steps per chunk
            uint32_t ah[4][4];
            const int chA = s * 2 + (lane >> 4);
#pragma unroll
            for (int i = 0; i < 4; i++) {
                const int r = warp_m + i * 16 + (lane & 15);
                const uint32_t off = r * 128 + ((chA ^ (r & 7)) << 4);
                ldsm4(ah[i], aB + off);
            }
            uint32_t bh[2][4];
            const int chB = s * 2 + ((lane >> 3) & 1);
#pragma unroll
            for (int j2 = 0; j2 < 2; j2++) {
                const int n = warp_n + j2 * 16 + (lane & 7) + ((lane >> 4) << 3);
                const uint32_t off = n * 128 + ((chB ^ (n & 7)) << 4);
                ldsm4(bh[j2], bB + off);
            }
#pragma unroll
            for (int i = 0; i < 4; i++)
#pragma unroll
                for (int j = 0; j < 4; j++)
                    mma16816(acc[i][j], ah[i], &bh[j >> 1][(j & 1) * 2]);
        }
        // next iteration's __syncthreads() guards the buffer swap
    }

    // ---- epilogue: bias + opt SiLU + fp16 store ----
#pragma unroll
    for (int i = 0; i < 4; i++) {
        const int r0 = m0 + warp_m + i * 16 + (lane >> 2);
#pragma unroll
        for (int j = 0; j < 4; j++) {
            const int col = n0 + warp_n + j * 8 + ((lane & 3) << 1);
            if (col < Nreal) {
                const float b0 = bias[col];
                const float b1 = bias[col + 1];
#pragma unroll
                for (int h = 0; h < 2; h++) {
                    const int r = r0 + h * 8;
                    float v0 = acc[i][j][h * 2 + 0] + b0;
                    float v1 = acc[i][j][h * 2 + 1] + b1;
                    if (ACT) {
                        v0 = v0 / (1.f + __expf(-v0));
                        v1 = v1 / (1.f + __expf(-v1));
                    }
                    const size_t ob = (size_t)r * Nreal + col;
                    *reinterpret_cast<__half2*>(oh + ob) =
                        __halves2half2(__float2half(v0), __float2half(v1));
                }
            }
        }
    }
}

// ---------------------------------------------------------------------------
// prep: x lower half -> fp16
// ---------------------------------------------------------------------------
__global__ void prep_x_kernel(const float* __restrict__ x,
                              __half* __restrict__ hx, int total)
{
    int idx = blockIdx.x * blockDim.x + threadIdx.x;
    if (idx >= total) return;
    int b = idx >> 6, j = idx & 63;
    hx[idx] = __float2half(x[(size_t)b * 128 + j]);
}

// ---------------------------------------------------------------------------
// Fused weight transpose: all 6 weights (both networks) in one launch.
// ---------------------------------------------------------------------------
__global__ __launch_bounds__(256)
void conv_all_kernel(const float* W1a, __half* T1a,
                     const float* W2a, __half* T2a,
                     const float* W3a, __half* T3a,
                     const float* W1b, __half* T1b,
                     const float* W2b, __half* T2b,
                     const float* W3b, __half* T3b)
{
    __shared__ float t[32][33];
    const int bid = blockIdx.x;

    const float* W; __half* Wt; int K, N, Npad, loc;
    if (bid < 32)        { W = W1a; Wt = T1a; K = 64;  N = 512;  Npad = 512;  loc = bid; }
    else if (bid < 288)  { W = W2a; Wt = T2a; K = 512; N = 512;  Npad = 512;  loc = bid - 32; }
    else if (bid < 1056) { W = W3a; Wt = T3a; K = 512; N = PDIM; Npad = PPAD; loc = bid - 288; }
    else if (bid < 1088) { W = W1b; Wt = T1b; K = 64;  N = 512;  Npad = 512;  loc = bid - 1056; }
    else if (bid < 1344) { W = W2b; Wt = T2b; K = 512; N = 512;  Npad = 512;  loc = bid - 1088; }
    else                 { W = W3b; Wt = T3b; K = 512; N = PDIM; Npad = PPAD; loc = bid - 1344; }

    const int tiles_x = Npad >> 5;
    const int n0 = (loc % tiles_x) * 32;
    const int k0 = (loc / tiles_x) * 32;
    const int tx = threadIdx.x & 31;
    const int ty = threadIdx.x >> 5;   // 0..7

    const int n = n0 + tx;
#pragma unroll
    for (int i = 0; i < 32; i += 8) {
        const int k = k0 + ty + i;
        t[ty + i][tx] = (n < N) ? W[(size_t)k * N + n] : 0.f;
    }
    __syncthreads();

#pragma unroll
    for (int i = 0; i < 32; i += 8) {
        const int nn = n0 + ty + i;
        const int kk = k0 + tx;
        Wt[(size_t)nn * K + kk] = __float2half(t[tx][ty + i]);
    }
}

// ---------------------------------------------------------------------------
// RQS spline + logdet. Params read as fp16 (coalesced, SMEM-staged).
// ---------------------------------------------------------------------------
__device__ __forceinline__ float softplusf(float v)
{
    return (v > 20.f) ? v : log1pf(expf(v));
}

__global__ __launch_bounds__(64)
void rqs_kernel(const float* __restrict__ x,
                const __half* __restrict__ params,
                __half* __restrict__ up,
                float* __restrict__ dout,
                float* __restrict__ ld_buf,
                int phase, int Bn)
{
    const int b = blockIdx.x;
    const int j = threadIdx.x;  // 0..63

    // stage the contiguous 1472-half param row: 184 uint4-of-8-halves chunks
    __shared__ __align__(16) __half sp[PDIM];
    {
        const uint4* src = reinterpret_cast<const uint4*>(
            params + (size_t)b * PDIM);
        uint4* dst = reinterpret_cast<uint4*>(sp);
#pragma unroll
        for (int i = 0; i < 3; i++) {
            const int q = i * 64 + j;
            if (q < PDIM / 8) dst[q] = src[q];
        }
    }
    const float xv = x[(size_t)b * 128 + (phase == 0 ? 64 + j : j)];
    __syncthreads();

    const __half* p = sp + j * 23;

    float W[8], H[8], D7[7];
#pragma unroll
    for (int i = 0; i < 8; i++) W[i] = __half2float(p[i]);
#pragma unroll
    for (int i = 0; i < 8; i++) H[i] = __half2float(p[8 + i]);
#pragma unroll
    for (int i = 0; i < 7; i++) D7[i] = __half2float(p[16 + i]);

    float mw = W[0];
#pragma unroll
    for (int i = 1; i < 8; i++) mw = fmaxf(mw, W[i]);
    float sw = 0.f;
#pragma unroll
    for (int i = 0; i < 8; i++) { W[i] = expf(W[i] - mw); sw += W[i]; }
    const float invw = 1.f / sw;

    float mh = H[0];
#pragma unroll
    for (int i = 1; i < 8; i++) mh = fmaxf(mh, H[i]);
    float sh = 0.f;
#pragma unroll
    for (int i = 0; i < 8; i++) { H[i] = expf(H[i] - mh); sh += H[i]; }
    const float invh = 1.f / sh;

    float cumw[9], cumh[9];
    cumw[0] = 0.f; cumh[0] = 0.f;
#pragma unroll
    for (int i = 0; i < 8; i++) {
        cumw[i + 1] = cumw[i] + (0.001f + 0.992f * W[i] * invw);
        cumh[i + 1] = cumh[i] + (0.001f + 0.992f * H[i] * invh);
    }
#pragma unroll
    for (int i = 0; i < 9; i++) {
        cumw[i] = 2.f * cumw[i] - 1.f;
        cumh[i] = 2.f * cumh[i] - 1.f;
    }
    cumw[0] = -1.f; cumw[8] = 1.f;
    cumh[0] = -1.f; cumh[8] = 1.f;

    float d[9];
    const float CST = logf(expf(1.0f - 0.001f) - 1.0f);
    const float dpad = 0.001f + softplusf(CST);
    d[0] = dpad; d[8] = dpad;
#pragma unroll
    for (int i = 0; i < 7; i++) d[i + 1] = 0.001f + softplusf(D7[i]);

    int idx = 0;
#pragma unroll
    for (int i = 0; i < 9; i++) {
        float loc = cumw[i] + ((i == 8) ? 1e-6f : 0.f);
        idx += (xv >= loc) ? 1 : 0;
    }
    idx -= 1;
    idx = max(0, min(7, idx));

    float icw = 0.f, iw = 1.f, ich = 0.f, ih = 1.f, d0 = 1.f, d1 = 1.f;
#pragma unroll
    for (int i = 0; i < 8; i++) {
        if (i == idx) {
            icw = cumw[i]; iw = cumw[i + 1] - cumw[i];
            ich = cumh[i]; ih = cumh[i + 1] - cumh[i];
            d0 = d[i]; d1 = d[i + 1];
        }
    }
    const float idel = ih / iw;
    const float th   = (xv - icw) / iw;
    const float omt  = 1.f - th;
    const float t1mt = th * omt;

    const float numer = ih * (idel * th * th + d0 * t1mt);
    const float den   = idel + (d0 + d1 - 2.f * idel) * t1mt;
    float out = ich + numer / den;

    const float dnum = idel * idel *
        (d1 * th * th + 2.f * idel * t1mt + d0 * omt * omt);
    float lad = logf(dnum) - 2.f * logf(den);

    const bool inside = (xv >= -1.f) && (xv <= 1.f);
    if (!inside) { out = xv; lad = 0.f; }

    if (phase == 0) {
        dout[(size_t)b * 128 + 64 + j] = out;
        up[(size_t)b * 64 + j] = __float2half(out);
    } else {
        dout[(size_t)b * 128 + j] = out;
    }

    float v = lad;
#pragma unroll
    for (int off = 16; off > 0; off >>= 1)
        v += __shfl_down_sync(0xffffffffu, v, off);
    __shared__ float sred[2];
    if ((j & 31) == 0) sred[j >> 5] = v;
    __syncthreads();
    if (j == 0) {
        const float tot = sred[0] + sred[1];
        if (phase == 0) ld_buf[b] = tot;
        else dout[(size_t)Bn * 128 + b] = ld_buf[b] + tot;
    }
}

// ---------------------------------------------------------------------------
// Launch
// ---------------------------------------------------------------------------
extern "C" void kernel_launch(void* const* d_in, const int* in_sizes, int n_in,
                              void* d_out, int out_size)
{
    const float* x    = (const float*)d_in[0];
    const float* f1w1 = (const float*)d_in[1];
    const float* f1b1 = (const float*)d_in[2];
    const float* f1w2 = (const float*)d_in[3];
    const float* f1b2 = (const float*)d_in[4];
    const float* f1w3 = (const float*)d_in[5];
    const float* f1b3 = (const float*)d_in[6];
    const float* f2w1 = (const float*)d_in[7];
    const float* f2b1 = (const float*)d_in[8];
    const float* f2w2 = (const float*)d_in[9];
    const float* f2b2 = (const float*)d_in[10];
    const float* f2w3 = (const float*)d_in[11];
    const float* f2b3 = (const float*)d_in[12];
    float* out = (float*)d_out;

    const int B = in_sizes[0] / 128;

    __half *xl, *up, *hA, *hB, *w1, *w2, *w3, *v1, *v2, *v3, *pa;
    float *ld;
    cudaGetSymbolAddress((void**)&xl, g_xl);
    cudaGetSymbolAddress((void**)&up, g_up);
    cudaGetSymbolAddress((void**)&hA, g_hA);
    cudaGetSymbolAddress((void**)&hB, g_hB);
    cudaGetSymbolAddress((void**)&w1, g_w1t);
    cudaGetSymbolAddress((void**)&w2, g_w2t);
    cudaGetSymbolAddress((void**)&w3, g_w3t);
    cudaGetSymbolAddress((void**)&v1, g_v1t);
    cudaGetSymbolAddress((void**)&v2, g_v2t);
    cudaGetSymbolAddress((void**)&v3, g_v3t);
    cudaGetSymbolAddress((void**)&pa, g_params);
    cudaGetSymbolAddress((void**)&ld, g_ld);

    const int DSMEM = 2 * STAGE_BYTES;  // 64 KB
    cudaFuncSetAttribute((const void*)gemm_hmma<1>,
                         cudaFuncAttributeMaxDynamicSharedMemorySize, DSMEM);
    cudaFuncSetAttribute((const void*)gemm_hmma<0>,
                         cudaFuncAttributeMaxDynamicSharedMemorySize, DSMEM);

    const int MB = B / 128;

    // prep + ALL weight conversions up front (independent of everything)
    prep_x_kernel<<<(B * 64 + 255) / 256, 256>>>(x, xl, B * 64);
    conv_all_kernel<<<2112, 256>>>(f1w1, w1, f1w2, w2, f1w3, w3,
                                   f2w1, v1, f2w2, v2, f2w3, v3);

    // ---- FCNN1 ----
    gemm_hmma<1><<<dim3(4, MB), 256, DSMEM>>>(xl, 64, w1, f1b1, hA, 512, 64);
    gemm_hmma<1><<<dim3(4, MB), 256, DSMEM>>>(hA, 512, w2, f1b2, hB, 512, 512);
    gemm_hmma<0><<<dim3(PPAD / 128, MB), 256, DSMEM>>>(hB, 512, w3, f1b3,
                                                       pa, PDIM, 512);

    rqs_kernel<<<B, 64>>>(x, pa, up, out, ld, 0, B);

    // ---- FCNN2 ----
    gemm_hmma<1><<<dim3(4, MB), 256, DSMEM>>>(up, 64, v1, f2b1, hA, 512, 64);
    gemm_hmma<1><<<dim3(4, MB), 256, DSMEM>>>(hA, 512, v2, f2b2, hB, 512, 512);
    gemm_hmma<0><<<dim3(PPAD / 128, MB), 256, DSMEM>>>(hB, 512, v3, f2b3,
                                                       pa, PDIM, 512);

    rqs_kernel<<<B, 64>>>(x, pa, nullptr, out, ld, 1, B);
}